// round 1
// baseline (speedup 1.0000x reference)
#include <cuda_runtime.h>
#include <cuda_bf16.h>
#include <math.h>

// Problem constants (fixed shapes from reference)
#define BB 2
#define NN 2048
#define DD 768
#define HH 12
#define HD 64
#define BH (BB*HH)

// scratch for Q,K,V in [b,h,n,hd] layout
__device__ float g_q[BH * NN * HD];
__device__ float g_k[BH * NN * HD];
__device__ float g_v[BH * NN * HD];

#define PAD 68  // padded stride (multiple of 4 for float4 alignment, kills read conflicts)

// ---------------------------------------------------------------------------
// QKV projection: y = x @ W.T  (W is [d_out, d_in] row-major -> K-major GEMM)
// Tiles: 64(M) x 64(N=one head) x 64(K). 256 threads, 4x4 per thread.
// z = 0/1/2 selects Wq/Wk/Wv and output buffer.
// ---------------------------------------------------------------------------
__global__ __launch_bounds__(256) void qkv_gemm_kernel(
    const float* __restrict__ x,
    const float* __restrict__ Wq,
    const float* __restrict__ Wk,
    const float* __restrict__ Wv)
{
    __shared__ float Xs[64][64];
    __shared__ float WsT[64][PAD];

    const float* W = (blockIdx.z == 0) ? Wq : (blockIdx.z == 1) ? Wk : Wv;
    float* outbuf  = (blockIdx.z == 0) ? g_q : (blockIdx.z == 1) ? g_k : g_v;

    const int tid = threadIdx.x;
    const int tx = tid & 15;        // 0..15 -> N (cols)
    const int ty = tid >> 4;        // 0..15 -> M (rows)
    const int tx4 = tx * 4, ty4 = ty * 4;

    const int h     = blockIdx.x;        // head index == N tile (64 cols/head)
    const int obase = h * 64;
    const int mbase = blockIdx.y * 64;

    float acc[4][4] = {};

    for (int kt = 0; kt < DD / 64; ++kt) {
        const int kb = kt * 64;
        #pragma unroll
        for (int i = 0; i < 16; ++i) {
            int idx = tid + i * 256;
            int r = idx >> 6, c = idx & 63;
            Xs[r][c]  = x[(size_t)(mbase + r) * DD + kb + c];
            WsT[c][r] = W[(size_t)(obase + r) * DD + kb + c];
        }
        __syncthreads();

        #pragma unroll 8
        for (int k = 0; k < 64; ++k) {
            float4 bv = *(const float4*)(&WsT[k][tx4]);
            float a0 = Xs[ty4 + 0][k];
            float a1 = Xs[ty4 + 1][k];
            float a2 = Xs[ty4 + 2][k];
            float a3 = Xs[ty4 + 3][k];
            acc[0][0] += a0 * bv.x; acc[0][1] += a0 * bv.y; acc[0][2] += a0 * bv.z; acc[0][3] += a0 * bv.w;
            acc[1][0] += a1 * bv.x; acc[1][1] += a1 * bv.y; acc[1][2] += a1 * bv.z; acc[1][3] += a1 * bv.w;
            acc[2][0] += a2 * bv.x; acc[2][1] += a2 * bv.y; acc[2][2] += a2 * bv.z; acc[2][3] += a2 * bv.w;
            acc[3][0] += a3 * bv.x; acc[3][1] += a3 * bv.y; acc[3][2] += a3 * bv.z; acc[3][3] += a3 * bv.w;
        }
        __syncthreads();
    }

    // store into [b, h, n, hd]
    #pragma unroll
    for (int i = 0; i < 4; ++i) {
        int m  = mbase + ty4 + i;          // global row in [0, B*N)
        int b  = m >> 11;                   // /2048
        int nn = m & (NN - 1);
        float* dst = outbuf + ((size_t)(b * HH + h) * NN + nn) * HD + tx4;
        dst[0] = acc[i][0]; dst[1] = acc[i][1]; dst[2] = acc[i][2]; dst[3] = acc[i][3];
    }
}

// ---------------------------------------------------------------------------
// Flash attention fp32, causal, UNSCALED logits.
// BLOCK_M = BLOCK_N = 64, HD = 64. 256 threads, 4x4 register tiles.
// Shared: Qs[64][64], KPs[64][PAD] (K^T then reused for P), Vs[64][64].
// ---------------------------------------------------------------------------
__device__ __forceinline__ float redmax16(float v) {
    v = fmaxf(v, __shfl_xor_sync(0xffffffffu, v, 8));
    v = fmaxf(v, __shfl_xor_sync(0xffffffffu, v, 4));
    v = fmaxf(v, __shfl_xor_sync(0xffffffffu, v, 2));
    v = fmaxf(v, __shfl_xor_sync(0xffffffffu, v, 1));
    return v;
}
__device__ __forceinline__ float redsum16(float v) {
    v += __shfl_xor_sync(0xffffffffu, v, 8);
    v += __shfl_xor_sync(0xffffffffu, v, 4);
    v += __shfl_xor_sync(0xffffffffu, v, 2);
    v += __shfl_xor_sync(0xffffffffu, v, 1);
    return v;
}

__global__ __launch_bounds__(256) void flash_kernel(float* __restrict__ out)
{
    extern __shared__ float sm[];
    float* Qs  = sm;                       // 64*64
    float* KPs = sm + 64 * 64;             // 64*PAD (K^T, then P)
    float* Vs  = sm + 64 * 64 + 64 * PAD;  // 64*64

    const int tid = threadIdx.x;
    const int tx = tid & 15, ty = tid >> 4;
    const int tx4 = tx * 4, ty4 = ty * 4;

    const int bh = blockIdx.y;
    const int qt = (int)gridDim.x - 1 - (int)blockIdx.x;   // heavy tiles first
    const int qbase = qt * 64;

    const float* Qb = g_q + (size_t)bh * NN * HD;
    const float* Kb = g_k + (size_t)bh * NN * HD;
    const float* Vb = g_v + (size_t)bh * NN * HD;

    // load Q tile
    #pragma unroll
    for (int i = 0; i < 16; ++i) {
        int idx = tid + i * 256;
        int r = idx >> 6, c = idx & 63;
        Qs[r * 64 + c] = Qb[(size_t)(qbase + r) * HD + c];
    }

    float oacc[4][4] = {};
    float mi[4], li[4];
    #pragma unroll
    for (int i = 0; i < 4; ++i) { mi[i] = -1e30f; li[i] = 0.0f; }

    for (int kt = 0; kt <= qt; ++kt) {
        const int kbase = kt * 64;
        __syncthreads();   // protect KPs/Vs consumers of previous iter (and Q load on iter 0)

        #pragma unroll
        for (int i = 0; i < 16; ++i) {
            int idx = tid + i * 256;
            int r = idx >> 6, c = idx & 63;
            KPs[c * PAD + r] = Kb[(size_t)(kbase + r) * HD + c];  // transposed
            Vs[r * 64 + c]   = Vb[(size_t)(kbase + r) * HD + c];
        }
        __syncthreads();

        // S = Q @ K^T  (4x4 per thread)
        float s[4][4] = {};
        #pragma unroll 8
        for (int d = 0; d < 64; ++d) {
            float4 kv = *(const float4*)(&KPs[d * PAD + tx4]);
            float q0 = Qs[(ty4 + 0) * 64 + d];
            float q1 = Qs[(ty4 + 1) * 64 + d];
            float q2 = Qs[(ty4 + 2) * 64 + d];
            float q3 = Qs[(ty4 + 3) * 64 + d];
            s[0][0] += q0 * kv.x; s[0][1] += q0 * kv.y; s[0][2] += q0 * kv.z; s[0][3] += q0 * kv.w;
            s[1][0] += q1 * kv.x; s[1][1] += q1 * kv.y; s[1][2] += q1 * kv.z; s[1][3] += q1 * kv.w;
            s[2][0] += q2 * kv.x; s[2][1] += q2 * kv.y; s[2][2] += q2 * kv.z; s[2][3] += q2 * kv.w;
            s[3][0] += q3 * kv.x; s[3][1] += q3 * kv.y; s[3][2] += q3 * kv.z; s[3][3] += q3 * kv.w;
        }

        // causal mask (only the diagonal tile needs it)
        if (kt == qt) {
            #pragma unroll
            for (int i = 0; i < 4; ++i) {
                int qg = qbase + ty4 + i;
                #pragma unroll
                for (int j = 0; j < 4; ++j) {
                    int kg = kbase + tx4 + j;
                    if (kg > qg) s[i][j] = -1e30f;
                }
            }
        }

        // online softmax update
        float al[4];
        #pragma unroll
        for (int i = 0; i < 4; ++i) {
            float r = fmaxf(fmaxf(s[i][0], s[i][1]), fmaxf(s[i][2], s[i][3]));
            r = redmax16(r);
            float mnew = fmaxf(mi[i], r);
            al[i] = __expf(mi[i] - mnew);
            mi[i] = mnew;
            s[i][0] = __expf(s[i][0] - mnew);
            s[i][1] = __expf(s[i][1] - mnew);
            s[i][2] = __expf(s[i][2] - mnew);
            s[i][3] = __expf(s[i][3] - mnew);
            float rs = s[i][0] + s[i][1] + s[i][2] + s[i][3];
            rs = redsum16(rs);
            li[i] = li[i] * al[i] + rs;
            oacc[i][0] *= al[i]; oacc[i][1] *= al[i]; oacc[i][2] *= al[i]; oacc[i][3] *= al[i];
        }

        __syncthreads();   // all S reads of KPs done -> safe to overwrite with P
        #pragma unroll
        for (int i = 0; i < 4; ++i) {
            *(float4*)(&KPs[(ty4 + i) * PAD + tx4]) = make_float4(s[i][0], s[i][1], s[i][2], s[i][3]);
        }
        __syncthreads();

        // O += P @ V
        #pragma unroll 8
        for (int kk = 0; kk < 64; ++kk) {
            float4 vv = *(const float4*)(&Vs[kk * 64 + tx4]);
            float p0 = KPs[(ty4 + 0) * PAD + kk];
            float p1 = KPs[(ty4 + 1) * PAD + kk];
            float p2 = KPs[(ty4 + 2) * PAD + kk];
            float p3 = KPs[(ty4 + 3) * PAD + kk];
            oacc[0][0] += p0 * vv.x; oacc[0][1] += p0 * vv.y; oacc[0][2] += p0 * vv.z; oacc[0][3] += p0 * vv.w;
            oacc[1][0] += p1 * vv.x; oacc[1][1] += p1 * vv.y; oacc[1][2] += p1 * vv.z; oacc[1][3] += p1 * vv.w;
            oacc[2][0] += p2 * vv.x; oacc[2][1] += p2 * vv.y; oacc[2][2] += p2 * vv.z; oacc[2][3] += p2 * vv.w;
            oacc[3][0] += p3 * vv.x; oacc[3][1] += p3 * vv.y; oacc[3][2] += p3 * vv.z; oacc[3][3] += p3 * vv.w;
        }
    }

    // epilogue: out[b, n, h*64 + c] = O / l
    const int b = bh / HH, h = bh % HH;
    #pragma unroll
    for (int i = 0; i < 4; ++i) {
        float inv = 1.0f / li[i];
        int q = qbase + ty4 + i;
        float* dst = out + ((size_t)(b * NN + q) * DD) + h * HD + tx4;
        dst[0] = oacc[i][0] * inv;
        dst[1] = oacc[i][1] * inv;
        dst[2] = oacc[i][2] * inv;
        dst[3] = oacc[i][3] * inv;
    }
}

static const int FLASH_SMEM = (64 * 64 + 64 * PAD + 64 * 64) * (int)sizeof(float); // 50176 B

extern "C" void kernel_launch(void* const* d_in, const int* in_sizes, int n_in,
                              void* d_out, int out_size)
{
    const float* x  = (const float*)d_in[0];
    const float* Wq = (const float*)d_in[1];
    const float* Wk = (const float*)d_in[2];
    const float* Wv = (const float*)d_in[3];
    float* out = (float*)d_out;

    cudaFuncSetAttribute(flash_kernel, cudaFuncAttributeMaxDynamicSharedMemorySize, FLASH_SMEM);

    // QKV projections: grid (heads=12, Mtiles=64, qkv=3)
    qkv_gemm_kernel<<<dim3(DD / 64, (BB * NN) / 64, 3), 256>>>(x, Wq, Wk, Wv);

    // causal flash attention: grid (qtiles=32, b*h=24)
    flash_kernel<<<dim3(NN / 64, BH), 256, FLASH_SMEM>>>(out);
}

// round 3
// speedup vs baseline: 1.4332x; 1.4332x over previous
#include <cuda_runtime.h>
#include <cuda_bf16.h>
#include <cstdint>
#include <math.h>

// Problem constants
#define BB 2
#define NN 2048
#define DD 768
#define HH 12
#define HD 64
#define BH (BB*HH)
#define XN (BB*NN*DD)
#define WN (DD*DD)

// fp32 scratch Q,K,V in [b,h,n,hd]
__device__ float g_q[BH * NN * HD];
__device__ float g_k[BH * NN * HD];
__device__ float g_v[BH * NN * HD];
// bf16 hi/lo splits
__device__ __align__(16) __nv_bfloat16 g_xhi[XN], g_xlo[XN];
__device__ __align__(16) __nv_bfloat16 g_whi[3 * WN], g_wlo[3 * WN];

__device__ __forceinline__ uint32_t smem_u32(const void* p) {
    uint32_t a;
    asm("{ .reg .u64 t; cvta.to.shared.u64 t, %1; cvt.u32.u64 %0, t; }" : "=r"(a) : "l"(p));
    return a;
}

// ---------------------------------------------------------------------------
// Split kernel: fp32 -> bf16 hi + bf16 lo residual
// ---------------------------------------------------------------------------
__device__ __forceinline__ uint32_t pack2(float a, float b) {
    __nv_bfloat162 t = __floats2bfloat162_rn(a, b);
    return *reinterpret_cast<uint32_t*>(&t);
}

__global__ __launch_bounds__(256) void split_kernel(
    const float4* __restrict__ x, const float4* __restrict__ Wq,
    const float4* __restrict__ Wk, const float4* __restrict__ Wv)
{
    const int nx = XN / 4, nw = WN / 4;
    int i = blockIdx.x * 256 + threadIdx.x;
    if (i >= nx + 3 * nw) return;

    float4 v;
    __nv_bfloat16 *hd, *ld;
    if (i < nx) {
        v = x[i];
        hd = g_xhi + (size_t)i * 4; ld = g_xlo + (size_t)i * 4;
    } else {
        int j = i - nx;
        int z = j / nw, r = j - z * nw;
        const float4* w = (z == 0) ? Wq : (z == 1) ? Wk : Wv;
        v = w[r];
        hd = g_whi + (size_t)z * WN + (size_t)r * 4;
        ld = g_wlo + (size_t)z * WN + (size_t)r * 4;
    }
    float h0 = __bfloat162float(__float2bfloat16_rn(v.x));
    float h1 = __bfloat162float(__float2bfloat16_rn(v.y));
    float h2 = __bfloat162float(__float2bfloat16_rn(v.z));
    float h3 = __bfloat162float(__float2bfloat16_rn(v.w));
    uint2 H = make_uint2(pack2(v.x, v.y), pack2(v.z, v.w));
    uint2 L = make_uint2(pack2(v.x - h0, v.y - h1), pack2(v.z - h2, v.w - h3));
    *reinterpret_cast<uint2*>(hd) = H;
    *reinterpret_cast<uint2*>(ld) = L;
}

// ---------------------------------------------------------------------------
// QKV GEMM via mma.sync bf16x3. CTA tile 128x128, 8 warps (64x32 each).
// K pipelined in 32-wide chunks, 2-stage cp.async double buffer.
// smem row stride 40 bf16 (80B) -> conflict-free ldmatrix.
// ---------------------------------------------------------------------------
#define KC 32
#define SROW 40                       // padded row stride in bf16 elems
#define TILE_B (128 * SROW * 2)       // 10240 bytes per tile
#define STAGE_B (4 * TILE_B)          // Ah, Al, Bh, Bl = 40960
#define NCHUNK (DD / KC)              // 24

__device__ __forceinline__ void cpa16(uint32_t dst, const void* src) {
    asm volatile("cp.async.cg.shared.global [%0], [%1], 16;" :: "r"(dst), "l"(src) : "memory");
}
__device__ __forceinline__ void cpa_commit() {
    asm volatile("cp.async.commit_group;" ::: "memory");
}
__device__ __forceinline__ void ldmx4(uint32_t* r, uint32_t addr) {
    asm volatile("ldmatrix.sync.aligned.m8n8.x4.shared.b16 {%0,%1,%2,%3}, [%4];"
        : "=r"(r[0]), "=r"(r[1]), "=r"(r[2]), "=r"(r[3]) : "r"(addr));
}
__device__ __forceinline__ void mma16816(float* c, const uint32_t* a, uint32_t b0, uint32_t b1) {
    asm volatile("mma.sync.aligned.m16n8k16.row.col.f32.bf16.bf16.f32 "
        "{%0,%1,%2,%3}, {%4,%5,%6,%7}, {%8,%9}, {%0,%1,%2,%3};"
        : "+f"(c[0]), "+f"(c[1]), "+f"(c[2]), "+f"(c[3])
        : "r"(a[0]), "r"(a[1]), "r"(a[2]), "r"(a[3]), "r"(b0), "r"(b1));
}

__global__ __launch_bounds__(256, 2) void qkv_mma_kernel()
{
    extern __shared__ char smc[];
    const uint32_t sb = smem_u32(smc);

    const int tid = threadIdx.x;
    const int w = tid >> 5, lane = tid & 31;
    const int wm = (w >> 2) * 64;      // warp M offset in CTA tile
    const int wn = (w & 3) * 32;       // warp N offset
    const int z = blockIdx.z;
    const int n0 = blockIdx.x * 128;
    const int m0 = blockIdx.y * 128;

    const __nv_bfloat16* __restrict__ Bh = g_whi + (size_t)z * WN;
    const __nv_bfloat16* __restrict__ Bl = g_wlo + (size_t)z * WN;

    // per-thread load indices (2 x uint4 per tile)
    const int id0 = tid, id1 = 256 + tid;
    const int r0 = id0 >> 2, c0 = id0 & 3;
    const int r1 = id1 >> 2, c1 = id1 & 3;

    auto load_chunk = [&](int kt, int stage) {
        const int kb = kt * KC;
        const uint32_t st = sb + stage * STAGE_B;
        {
            uint32_t doff = (uint32_t)(r0 * 80 + c0 * 16);
            size_t gA = (size_t)(m0 + r0) * DD + kb + c0 * 8;
            size_t gB = (size_t)(n0 + r0) * DD + kb + c0 * 8;
            cpa16(st + 0 * TILE_B + doff, g_xhi + gA);
            cpa16(st + 1 * TILE_B + doff, g_xlo + gA);
            cpa16(st + 2 * TILE_B + doff, Bh + gB);
            cpa16(st + 3 * TILE_B + doff, Bl + gB);
        }
        {
            uint32_t doff = (uint32_t)(r1 * 80 + c1 * 16);
            size_t gA = (size_t)(m0 + r1) * DD + kb + c1 * 8;
            size_t gB = (size_t)(n0 + r1) * DD + kb + c1 * 8;
            cpa16(st + 0 * TILE_B + doff, g_xhi + gA);
            cpa16(st + 1 * TILE_B + doff, g_xlo + gA);
            cpa16(st + 2 * TILE_B + doff, Bh + gB);
            cpa16(st + 3 * TILE_B + doff, Bl + gB);
        }
        cpa_commit();
    };

    float acc[4][4][4] = {};   // [fm][fn][reg]

    load_chunk(0, 0);
    load_chunk(1, 1);

    // ldmatrix address components (row = base + (lane&15), col = khalf*8)
    const int lrow = lane & 15;
    const int lcol = ((lane >> 4) & 1) * 8;

    for (int kt = 0; kt < NCHUNK; ++kt) {
        if (kt < NCHUNK - 1)
            asm volatile("cp.async.wait_group 1;" ::: "memory");
        else
            asm volatile("cp.async.wait_group 0;" ::: "memory");
        __syncthreads();

        const uint32_t st = sb + (kt & 1) * STAGE_B;

        #pragma unroll
        for (int ks = 0; ks < 2; ++ks) {
            const int kc = ks * 16 + lcol;
            uint32_t ah[4][4], al[4][4];
            #pragma unroll
            for (int fm = 0; fm < 4; ++fm) {
                uint32_t off = (uint32_t)((wm + fm * 16 + lrow) * SROW + kc) * 2;
                ldmx4(ah[fm], st + 0 * TILE_B + off);
                ldmx4(al[fm], st + 1 * TILE_B + off);
            }
            uint32_t bh[2][4], bl[2][4];
            #pragma unroll
            for (int fp = 0; fp < 2; ++fp) {
                uint32_t off = (uint32_t)((wn + fp * 16 + lrow) * SROW + kc) * 2;
                ldmx4(bh[fp], st + 2 * TILE_B + off);
                ldmx4(bl[fp], st + 3 * TILE_B + off);
            }
            #pragma unroll
            for (int fm = 0; fm < 4; ++fm) {
                #pragma unroll
                for (int fn = 0; fn < 4; ++fn) {
                    const int p = fn >> 1, f = fn & 1;
                    mma16816(acc[fm][fn], ah[fm], bh[p][f], bh[p][f + 2]); // hi*hi
                    mma16816(acc[fm][fn], ah[fm], bl[p][f], bl[p][f + 2]); // hi*lo
                    mma16816(acc[fm][fn], al[fm], bh[p][f], bh[p][f + 2]); // lo*hi
                }
            }
        }
        __syncthreads();
        if (kt + 2 < NCHUNK) load_chunk(kt + 2, kt & 1);
    }

    // epilogue: store to [b,h,n,hd]
    float* outbuf = (z == 0) ? g_q : (z == 1) ? g_k : g_v;
    const int trow = lane >> 2;
    const int tcol = (lane & 3) * 2;
    #pragma unroll
    for (int fm = 0; fm < 4; ++fm) {
        #pragma unroll
        for (int fn = 0; fn < 4; ++fn) {
            int o = n0 + wn + fn * 8 + tcol;
            int h = o >> 6, cb = o & 63;
            #pragma unroll
            for (int half = 0; half < 2; ++half) {
                int row = m0 + wm + fm * 16 + trow + half * 8;
                int b = row >> 11, n = row & (NN - 1);
                float* dp = outbuf + (((size_t)(b * HH + h)) * NN + n) * HD + cb;
                float2 v = make_float2(acc[fm][fn][half * 2], acc[fm][fn][half * 2 + 1]);
                *reinterpret_cast<float2*>(dp) = v;
            }
        }
    }
}

// ---------------------------------------------------------------------------
// Flash attention: fp32, causal, unscaled. 64x64 blocks, 128 threads,
// 8x4 thread tiles; Q and P stored transposed -> all operands LDS.128.
// ---------------------------------------------------------------------------
#define FPAD 68

__global__ __launch_bounds__(128) void flash2_kernel(float* __restrict__ out)
{
    extern __shared__ float sm[];
    float* Qt = sm;                 // [64][FPAD]  Q^T
    float* KP = sm + 64 * FPAD;     // [64][FPAD]  K^T, then P^T
    float* Vs = sm + 2 * 64 * FPAD; // [64][64]

    const int tid = threadIdx.x;
    const int tx = tid & 15, ty = tid >> 4;
    const int tx4 = tx * 4, ty8 = ty * 8;

    const int bh = blockIdx.y;
    const int qt = (int)gridDim.x - 1 - (int)blockIdx.x;
    const int qbase = qt * 64;

    const float* __restrict__ Qb = g_q + (size_t)bh * NN * HD;
    const float* __restrict__ Kb = g_k + (size_t)bh * NN * HD;
    const float* __restrict__ Vb = g_v + (size_t)bh * NN * HD;

    #pragma unroll
    for (int i = 0; i < 8; ++i) {
        int id = tid + i * 128;
        int r = id >> 4, c4 = (id & 15) * 4;
        float4 v = *reinterpret_cast<const float4*>(Qb + (size_t)(qbase + r) * HD + c4);
        Qt[(c4 + 0) * FPAD + r] = v.x;
        Qt[(c4 + 1) * FPAD + r] = v.y;
        Qt[(c4 + 2) * FPAD + r] = v.z;
        Qt[(c4 + 3) * FPAD + r] = v.w;
    }

    float o[8][4] = {};
    float mi[8], li[8];
    #pragma unroll
    for (int i = 0; i < 8; ++i) { mi[i] = -1e30f; li[i] = 0.0f; }

    for (int kt = 0; kt <= qt; ++kt) {
        const int kbase = kt * 64;
        __syncthreads();

        #pragma unroll
        for (int i = 0; i < 8; ++i) {
            int id = tid + i * 128;
            int r = id >> 4, c4 = (id & 15) * 4;
            float4 kv = *reinterpret_cast<const float4*>(Kb + (size_t)(kbase + r) * HD + c4);
            KP[(c4 + 0) * FPAD + r] = kv.x;
            KP[(c4 + 1) * FPAD + r] = kv.y;
            KP[(c4 + 2) * FPAD + r] = kv.z;
            KP[(c4 + 3) * FPAD + r] = kv.w;
            *reinterpret_cast<float4*>(Vs + r * 64 + c4) =
                *reinterpret_cast<const float4*>(Vb + (size_t)(kbase + r) * HD + c4);
        }
        __syncthreads();

        float s[8][4] = {};
        #pragma unroll 4
        for (int d = 0; d < 64; ++d) {
            float4 kv = *reinterpret_cast<const float4*>(KP + d * FPAD + tx4);
            float4 qa = *reinterpret_cast<const float4*>(Qt + d * FPAD + ty8);
            float4 qb = *reinterpret_cast<const float4*>(Qt + d * FPAD + ty8 + 4);
            float qv[8] = {qa.x, qa.y, qa.z, qa.w, qb.x, qb.y, qb.z, qb.w};
            float kvv[4] = {kv.x, kv.y, kv.z, kv.w};
            #pragma unroll
            for (int i = 0; i < 8; ++i)
                #pragma unroll
                for (int j = 0; j < 4; ++j)
                    s[i][j] += qv[i] * kvv[j];
        }

        if (kt == qt) {
            #pragma unroll
            for (int i = 0; i < 8; ++i) {
                int qg = qbase + ty8 + i;
                #pragma unroll
                for (int j = 0; j < 4; ++j)
                    if (kbase + tx4 + j > qg) s[i][j] = -1e30f;
            }
        }

        float al[8];
        #pragma unroll
        for (int i = 0; i < 8; ++i) {
            float r = fmaxf(fmaxf(s[i][0], s[i][1]), fmaxf(s[i][2], s[i][3]));
            r = fmaxf(r, __shfl_xor_sync(0xffffffffu, r, 8));
            r = fmaxf(r, __shfl_xor_sync(0xffffffffu, r, 4));
            r = fmaxf(r, __shfl_xor_sync(0xffffffffu, r, 2));
            r = fmaxf(r, __shfl_xor_sync(0xffffffffu, r, 1));
            float mnew = fmaxf(mi[i], r);
            al[i] = __expf(mi[i] - mnew);
            mi[i] = mnew;
            s[i][0] = __expf(s[i][0] - mnew);
            s[i][1] = __expf(s[i][1] - mnew);
            s[i][2] = __expf(s[i][2] - mnew);
            s[i][3] = __expf(s[i][3] - mnew);
            float rs = (s[i][0] + s[i][1]) + (s[i][2] + s[i][3]);
            rs += __shfl_xor_sync(0xffffffffu, rs, 8);
            rs += __shfl_xor_sync(0xffffffffu, rs, 4);
            rs += __shfl_xor_sync(0xffffffffu, rs, 2);
            rs += __shfl_xor_sync(0xffffffffu, rs, 1);
            li[i] = li[i] * al[i] + rs;
            o[i][0] *= al[i]; o[i][1] *= al[i]; o[i][2] *= al[i]; o[i][3] *= al[i];
        }

        __syncthreads();
        #pragma unroll
        for (int j = 0; j < 4; ++j) {
            *reinterpret_cast<float4*>(KP + (tx4 + j) * FPAD + ty8) =
                make_float4(s[0][j], s[1][j], s[2][j], s[3][j]);
            *reinterpret_cast<float4*>(KP + (tx4 + j) * FPAD + ty8 + 4) =
                make_float4(s[4][j], s[5][j], s[6][j], s[7][j]);
        }
        __syncthreads();

        #pragma unroll 4
        for (int kk = 0; kk < 64; ++kk) {
            float4 vv = *reinterpret_cast<const float4*>(Vs + kk * 64 + tx4);
            float4 pa = *reinterpret_cast<const float4*>(KP + kk * FPAD + ty8);
            float4 pb = *reinterpret_cast<const float4*>(KP + kk * FPAD + ty8 + 4);
            float pv[8] = {pa.x, pa.y, pa.z, pa.w, pb.x, pb.y, pb.z, pb.w};
            float vvv[4] = {vv.x, vv.y, vv.z, vv.w};
            #pragma unroll
            for (int i = 0; i < 8; ++i)
                #pragma unroll
                for (int j = 0; j < 4; ++j)
                    o[i][j] += pv[i] * vvv[j];
        }
    }

    const int b = bh / HH, h = bh % HH;
    #pragma unroll
    for (int i = 0; i < 8; ++i) {
        float inv = 1.0f / li[i];
        int q = qbase + ty8 + i;
        float* dst = out + ((size_t)(b * NN + q)) * DD + h * HD + tx4;
        *reinterpret_cast<float4*>(dst) =
            make_float4(o[i][0] * inv, o[i][1] * inv, o[i][2] * inv, o[i][3] * inv);
    }
}

static const int GEMM_SMEM  = 2 * STAGE_B;                                    // 81920
static const int FLASH_SMEM = (2 * 64 * FPAD + 64 * 64) * (int)sizeof(float); // 51200

extern "C" void kernel_launch(void* const* d_in, const int* in_sizes, int n_in,
                              void* d_out, int out_size)
{
    const float* x  = (const float*)d_in[0];
    const float* Wq = (const float*)d_in[1];
    const float* Wk = (const float*)d_in[2];
    const float* Wv = (const float*)d_in[3];
    float* out = (float*)d_out;

    cudaFuncSetAttribute(qkv_mma_kernel, cudaFuncAttributeMaxDynamicSharedMemorySize, GEMM_SMEM);
    cudaFuncSetAttribute(flash2_kernel, cudaFuncAttributeMaxDynamicSharedMemorySize, FLASH_SMEM);

    int total4 = XN / 4 + 3 * (WN / 4);
    split_kernel<<<(total4 + 255) / 256, 256>>>(
        (const float4*)x, (const float4*)Wq, (const float4*)Wk, (const float4*)Wv);

    qkv_mma_kernel<<<dim3(DD / 128, (BB * NN) / 128, 3), 256, GEMM_SMEM>>>();

    flash2_kernel<<<dim3(NN / 64, BH), 128, FLASH_SMEM>>>(out);
}

// round 4
// speedup vs baseline: 2.7068x; 1.8887x over previous
#include <cuda_runtime.h>
#include <cuda_bf16.h>
#include <cstdint>
#include <math.h>

// Problem constants
#define BB 2
#define NN 2048
#define DD 768
#define HH 12
#define HD 64
#define BH (BB*HH)
#define XN (BB*NN*DD)
#define WN (DD*DD)

// bf16 hi/lo splits of inputs
__device__ __align__(16) __nv_bfloat16 g_xhi[XN], g_xlo[XN];
__device__ __align__(16) __nv_bfloat16 g_whi[3 * WN], g_wlo[3 * WN];
// bf16 hi/lo Q,K,V in [b,h,n,hd]
__device__ __align__(16) __nv_bfloat16 g_qhi[BH*NN*HD], g_qlo[BH*NN*HD];
__device__ __align__(16) __nv_bfloat16 g_khi[BH*NN*HD], g_klo[BH*NN*HD];
__device__ __align__(16) __nv_bfloat16 g_vhi[BH*NN*HD], g_vlo[BH*NN*HD];

__device__ __forceinline__ uint32_t smem_u32(const void* p) {
    uint32_t a;
    asm("{ .reg .u64 t; cvta.to.shared.u64 t, %1; cvt.u32.u64 %0, t; }" : "=r"(a) : "l"(p));
    return a;
}
__device__ __forceinline__ uint32_t pack2(float a, float b) {
    __nv_bfloat162 t = __floats2bfloat162_rn(a, b);
    return *reinterpret_cast<uint32_t*>(&t);
}
__device__ __forceinline__ void split2(float a, float b, uint32_t& hp, uint32_t& lp) {
    __nv_bfloat16 ha = __float2bfloat16_rn(a), hb = __float2bfloat16_rn(b);
    __nv_bfloat162 hh; hh.x = ha; hh.y = hb;
    hp = *reinterpret_cast<uint32_t*>(&hh);
    lp = pack2(a - __bfloat162float(ha), b - __bfloat162float(hb));
}

__device__ __forceinline__ void cpa16(uint32_t dst, const void* src) {
    asm volatile("cp.async.cg.shared.global [%0], [%1], 16;" :: "r"(dst), "l"(src) : "memory");
}
__device__ __forceinline__ void cpa_commit() {
    asm volatile("cp.async.commit_group;" ::: "memory");
}
__device__ __forceinline__ void ldmx4(uint32_t* r, uint32_t addr) {
    asm volatile("ldmatrix.sync.aligned.m8n8.x4.shared.b16 {%0,%1,%2,%3}, [%4];"
        : "=r"(r[0]), "=r"(r[1]), "=r"(r[2]), "=r"(r[3]) : "r"(addr));
}
__device__ __forceinline__ void ldmx4t(uint32_t* r, uint32_t addr) {
    asm volatile("ldmatrix.sync.aligned.m8n8.x4.trans.shared.b16 {%0,%1,%2,%3}, [%4];"
        : "=r"(r[0]), "=r"(r[1]), "=r"(r[2]), "=r"(r[3]) : "r"(addr));
}
__device__ __forceinline__ void mma16816(float* c, const uint32_t* a, uint32_t b0, uint32_t b1) {
    asm volatile("mma.sync.aligned.m16n8k16.row.col.f32.bf16.bf16.f32 "
        "{%0,%1,%2,%3}, {%4,%5,%6,%7}, {%8,%9}, {%0,%1,%2,%3};"
        : "+f"(c[0]), "+f"(c[1]), "+f"(c[2]), "+f"(c[3])
        : "r"(a[0]), "r"(a[1]), "r"(a[2]), "r"(a[3]), "r"(b0), "r"(b1));
}

// ---------------------------------------------------------------------------
// Split kernel: fp32 -> bf16 hi + lo residual (x and the three W)
// ---------------------------------------------------------------------------
__global__ __launch_bounds__(256) void split_kernel(
    const float4* __restrict__ x, const float4* __restrict__ Wq,
    const float4* __restrict__ Wk, const float4* __restrict__ Wv)
{
    const int nx = XN / 4, nw = WN / 4;
    int i = blockIdx.x * 256 + threadIdx.x;
    if (i >= nx + 3 * nw) return;

    float4 v;
    __nv_bfloat16 *hd, *ld;
    if (i < nx) {
        v = x[i];
        hd = g_xhi + (size_t)i * 4; ld = g_xlo + (size_t)i * 4;
    } else {
        int j = i - nx;
        int z = j / nw, r = j - z * nw;
        const float4* w = (z == 0) ? Wq : (z == 1) ? Wk : Wv;
        v = w[r];
        hd = g_whi + (size_t)z * WN + (size_t)r * 4;
        ld = g_wlo + (size_t)z * WN + (size_t)r * 4;
    }
    uint32_t h0, l0, h1, l1;
    split2(v.x, v.y, h0, l0);
    split2(v.z, v.w, h1, l1);
    *reinterpret_cast<uint2*>(hd) = make_uint2(h0, h1);
    *reinterpret_cast<uint2*>(ld) = make_uint2(l0, l1);
}

// ---------------------------------------------------------------------------
// QKV GEMM via mma.sync bf16x3; epilogue writes bf16 hi/lo Q,K,V.
// ---------------------------------------------------------------------------
#define KC 32
#define SROW 40
#define TILE_B (128 * SROW * 2)
#define STAGE_B (4 * TILE_B)
#define NCHUNK (DD / KC)

__global__ __launch_bounds__(256, 2) void qkv_mma_kernel()
{
    extern __shared__ char smc[];
    const uint32_t sb = smem_u32(smc);

    const int tid = threadIdx.x;
    const int w = tid >> 5, lane = tid & 31;
    const int wm = (w >> 2) * 64;
    const int wn = (w & 3) * 32;
    const int z = blockIdx.z;
    const int n0 = blockIdx.x * 128;
    const int m0 = blockIdx.y * 128;

    const __nv_bfloat16* __restrict__ Bh = g_whi + (size_t)z * WN;
    const __nv_bfloat16* __restrict__ Bl = g_wlo + (size_t)z * WN;

    const int id0 = tid, id1 = 256 + tid;
    const int r0 = id0 >> 2, c0 = id0 & 3;
    const int r1 = id1 >> 2, c1 = id1 & 3;

    auto load_chunk = [&](int kt, int stage) {
        const int kb = kt * KC;
        const uint32_t st = sb + stage * STAGE_B;
        {
            uint32_t doff = (uint32_t)(r0 * 80 + c0 * 16);
            size_t gA = (size_t)(m0 + r0) * DD + kb + c0 * 8;
            size_t gB = (size_t)(n0 + r0) * DD + kb + c0 * 8;
            cpa16(st + 0 * TILE_B + doff, g_xhi + gA);
            cpa16(st + 1 * TILE_B + doff, g_xlo + gA);
            cpa16(st + 2 * TILE_B + doff, Bh + gB);
            cpa16(st + 3 * TILE_B + doff, Bl + gB);
        }
        {
            uint32_t doff = (uint32_t)(r1 * 80 + c1 * 16);
            size_t gA = (size_t)(m0 + r1) * DD + kb + c1 * 8;
            size_t gB = (size_t)(n0 + r1) * DD + kb + c1 * 8;
            cpa16(st + 0 * TILE_B + doff, g_xhi + gA);
            cpa16(st + 1 * TILE_B + doff, g_xlo + gA);
            cpa16(st + 2 * TILE_B + doff, Bh + gB);
            cpa16(st + 3 * TILE_B + doff, Bl + gB);
        }
        cpa_commit();
    };

    float acc[4][4][4] = {};

    load_chunk(0, 0);
    load_chunk(1, 1);

    const int lrow = lane & 15;
    const int lcol = ((lane >> 4) & 1) * 8;

    for (int kt = 0; kt < NCHUNK; ++kt) {
        if (kt < NCHUNK - 1)
            asm volatile("cp.async.wait_group 1;" ::: "memory");
        else
            asm volatile("cp.async.wait_group 0;" ::: "memory");
        __syncthreads();

        const uint32_t st = sb + (kt & 1) * STAGE_B;

        #pragma unroll
        for (int ks = 0; ks < 2; ++ks) {
            const int kc = ks * 16 + lcol;
            uint32_t ah[4][4], al[4][4];
            #pragma unroll
            for (int fm = 0; fm < 4; ++fm) {
                uint32_t off = (uint32_t)((wm + fm * 16 + lrow) * SROW + kc) * 2;
                ldmx4(ah[fm], st + 0 * TILE_B + off);
                ldmx4(al[fm], st + 1 * TILE_B + off);
            }
            uint32_t bh[2][4], bl[2][4];
            #pragma unroll
            for (int fp = 0; fp < 2; ++fp) {
                uint32_t off = (uint32_t)((wn + fp * 16 + lrow) * SROW + kc) * 2;
                ldmx4(bh[fp], st + 2 * TILE_B + off);
                ldmx4(bl[fp], st + 3 * TILE_B + off);
            }
            #pragma unroll
            for (int fm = 0; fm < 4; ++fm) {
                #pragma unroll
                for (int fn = 0; fn < 4; ++fn) {
                    const int p = fn >> 1, f = fn & 1;
                    mma16816(acc[fm][fn], ah[fm], bh[p][f], bh[p][f + 2]);
                    mma16816(acc[fm][fn], ah[fm], bl[p][f], bl[p][f + 2]);
                    mma16816(acc[fm][fn], al[fm], bh[p][f], bh[p][f + 2]);
                }
            }
        }
        __syncthreads();
        if (kt + 2 < NCHUNK) load_chunk(kt + 2, kt & 1);
    }

    // epilogue: split to bf16 hi/lo, store to [b,h,n,hd]
    __nv_bfloat16* Oh = (z == 0) ? g_qhi : (z == 1) ? g_khi : g_vhi;
    __nv_bfloat16* Ol = (z == 0) ? g_qlo : (z == 1) ? g_klo : g_vlo;
    const int trow = lane >> 2;
    const int tcol = (lane & 3) * 2;
    #pragma unroll
    for (int fm = 0; fm < 4; ++fm) {
        #pragma unroll
        for (int fn = 0; fn < 4; ++fn) {
            int o = n0 + wn + fn * 8 + tcol;
            int h = o >> 6, cb = o & 63;
            #pragma unroll
            for (int half = 0; half < 2; ++half) {
                int row = m0 + wm + fm * 16 + trow + half * 8;
                int b = row >> 11, n = row & (NN - 1);
                size_t idx = (((size_t)(b * HH + h)) * NN + n) * HD + cb;
                uint32_t hp, lp;
                split2(acc[fm][fn][half * 2], acc[fm][fn][half * 2 + 1], hp, lp);
                *reinterpret_cast<uint32_t*>(Oh + idx) = hp;
                *reinterpret_cast<uint32_t*>(Ol + idx) = lp;
            }
        }
    }
}

// ---------------------------------------------------------------------------
// Flash attention on mma.sync bf16x3. BLOCK_M=128 (8 warps x 16 rows),
// BLOCK_N=64. K/V hi/lo double-buffered via cp.async; P stays in registers.
// ---------------------------------------------------------------------------
#define VROW 72                     // padded row stride in bf16 elems (144B)
#define KVTILE_B (64 * VROW * 2)    // 9216
#define KVSTAGE_B (4 * KVTILE_B)    // 36864

__global__ __launch_bounds__(256) void flash_mma_kernel(float* __restrict__ out)
{
    extern __shared__ char smc[];
    const uint32_t sb = smem_u32(smc);
    const int tid = threadIdx.x, wid = tid >> 5, lane = tid & 31;
    const int bh = blockIdx.y;
    const int qt = (int)gridDim.x - 1 - (int)blockIdx.x;   // heavy tiles first
    const int qbase = qt * 128;
    const int wm = wid * 16;

    const size_t base = (size_t)bh * NN * HD;
    const __nv_bfloat16* __restrict__ Qh = g_qhi + base;
    const __nv_bfloat16* __restrict__ Ql = g_qlo + base;
    const __nv_bfloat16* __restrict__ Kh = g_khi + base;
    const __nv_bfloat16* __restrict__ Kl = g_klo + base;
    const __nv_bfloat16* __restrict__ Vh = g_vhi + base;
    const __nv_bfloat16* __restrict__ Vl = g_vlo + base;

    // Q fragments (held in regs for whole kernel)
    uint32_t qh[4][4], ql[4][4];
    {
        const int r0 = qbase + wm + (lane >> 2);
        const int c0 = (lane & 3) * 2;
        #pragma unroll
        for (int kk = 0; kk < 4; ++kk) {
            #pragma unroll
            for (int j = 0; j < 4; ++j) {
                int row = r0 + (j & 1) * 8;
                int col = kk * 16 + c0 + (j >> 1) * 8;
                qh[kk][j] = *reinterpret_cast<const uint32_t*>(Qh + (size_t)row * HD + col);
                ql[kk][j] = *reinterpret_cast<const uint32_t*>(Ql + (size_t)row * HD + col);
            }
        }
    }

    auto load_kv = [&](int j, int stage) {
        const int kb = j * 64;
        const uint32_t st = sb + stage * KVSTAGE_B;
        #pragma unroll
        for (int i = 0; i < 8; ++i) {
            const int tile = i >> 1;            // 0:Kh 1:Kl 2:Vh 3:Vl
            const int rem = (i & 1) * 256 + tid;
            const int r = rem >> 3, c = rem & 7;
            uint32_t dst = st + tile * KVTILE_B + (uint32_t)(r * 144 + c * 16);
            const __nv_bfloat16* src = (tile == 0) ? Kh : (tile == 1) ? Kl
                                     : (tile == 2) ? Vh : Vl;
            cpa16(dst, src + (size_t)(kb + r) * HD + c * 8);
        }
        cpa_commit();
    };

    float o[8][4] = {};
    float mi0 = -1e30f, mi1 = -1e30f, li0 = 0.0f, li1 = 0.0f;

    const int ntiles = 2 * qt + 2;
    load_kv(0, 0);
    if (ntiles > 1) load_kv(1, 1);

    const int lrow = lane & 15;
    const int lcol = ((lane >> 4) & 1) * 8;
    // V trans ldmatrix address components
    const int vrow_base = (lane & 7) + ((lane >> 3) & 1) * 8;
    const int vcol = ((lane >> 4) & 1) * 8;

    for (int j = 0; j < ntiles; ++j) {
        if (j < ntiles - 1)
            asm volatile("cp.async.wait_group 1;" ::: "memory");
        else
            asm volatile("cp.async.wait_group 0;" ::: "memory");
        __syncthreads();

        const bool active = (64 * j <= qbase + wm + 15);   // not fully masked
        const uint32_t st = sb + (j & 1) * KVSTAGE_B;

        if (active) {
            // ---- S = Q K^T (bf16x3) ----
            float s[8][4] = {};
            #pragma unroll
            for (int kk = 0; kk < 4; ++kk) {
                const int kc = kk * 16 + lcol;
                uint32_t bkh[4][4], bkl[4][4];
                #pragma unroll
                for (int np = 0; np < 4; ++np) {
                    uint32_t off = (uint32_t)((np * 16 + lrow) * VROW + kc) * 2;
                    ldmx4(bkh[np], st + 0 * KVTILE_B + off);
                    ldmx4(bkl[np], st + 1 * KVTILE_B + off);
                }
                #pragma unroll
                for (int fn = 0; fn < 8; ++fn) {
                    const int np = fn >> 1, f = fn & 1;
                    mma16816(s[fn], qh[kk], bkh[np][f], bkh[np][f + 2]);
                    mma16816(s[fn], qh[kk], bkl[np][f], bkl[np][f + 2]);
                    mma16816(s[fn], ql[kk], bkh[np][f], bkh[np][f + 2]);
                }
            }

            // ---- causal mask (only near-diagonal tiles) ----
            if (64 * j + 63 > qbase + wm) {
                const int rg0 = qbase + wm + (lane >> 2);
                #pragma unroll
                for (int fn = 0; fn < 8; ++fn) {
                    const int cb = j * 64 + fn * 8 + (lane & 3) * 2;
                    if (cb + 0 > rg0)     s[fn][0] = -1e30f;
                    if (cb + 1 > rg0)     s[fn][1] = -1e30f;
                    if (cb + 0 > rg0 + 8) s[fn][2] = -1e30f;
                    if (cb + 1 > rg0 + 8) s[fn][3] = -1e30f;
                }
            }

            // ---- online softmax (rows r0 = lane>>2, r1 = r0+8) ----
            float m0n = mi0, m1n = mi1;
            #pragma unroll
            for (int fn = 0; fn < 8; ++fn) {
                m0n = fmaxf(m0n, fmaxf(s[fn][0], s[fn][1]));
                m1n = fmaxf(m1n, fmaxf(s[fn][2], s[fn][3]));
            }
            m0n = fmaxf(m0n, __shfl_xor_sync(0xffffffffu, m0n, 1));
            m0n = fmaxf(m0n, __shfl_xor_sync(0xffffffffu, m0n, 2));
            m1n = fmaxf(m1n, __shfl_xor_sync(0xffffffffu, m1n, 1));
            m1n = fmaxf(m1n, __shfl_xor_sync(0xffffffffu, m1n, 2));

            const float al0 = __expf(mi0 - m0n);
            const float al1 = __expf(mi1 - m1n);
            mi0 = m0n; mi1 = m1n;

            float rs0 = 0.0f, rs1 = 0.0f;
            #pragma unroll
            for (int fn = 0; fn < 8; ++fn) {
                s[fn][0] = __expf(s[fn][0] - m0n);
                s[fn][1] = __expf(s[fn][1] - m0n);
                s[fn][2] = __expf(s[fn][2] - m1n);
                s[fn][3] = __expf(s[fn][3] - m1n);
                rs0 += s[fn][0] + s[fn][1];
                rs1 += s[fn][2] + s[fn][3];
            }
            rs0 += __shfl_xor_sync(0xffffffffu, rs0, 1);
            rs0 += __shfl_xor_sync(0xffffffffu, rs0, 2);
            rs1 += __shfl_xor_sync(0xffffffffu, rs1, 1);
            rs1 += __shfl_xor_sync(0xffffffffu, rs1, 2);
            li0 = li0 * al0 + rs0;
            li1 = li1 * al1 + rs1;

            #pragma unroll
            for (int fn = 0; fn < 8; ++fn) {
                o[fn][0] *= al0; o[fn][1] *= al0;
                o[fn][2] *= al1; o[fn][3] *= al1;
            }

            // ---- O += P V (bf16x3; P from registers) ----
            #pragma unroll
            for (int kk = 0; kk < 4; ++kk) {
                uint32_t ph[4], pl[4];
                split2(s[2*kk    ][0], s[2*kk    ][1], ph[0], pl[0]);
                split2(s[2*kk    ][2], s[2*kk    ][3], ph[1], pl[1]);
                split2(s[2*kk + 1][0], s[2*kk + 1][1], ph[2], pl[2]);
                split2(s[2*kk + 1][2], s[2*kk + 1][3], ph[3], pl[3]);

                #pragma unroll
                for (int dp = 0; dp < 4; ++dp) {
                    const int vrow = kk * 16 + vrow_base;
                    uint32_t off = (uint32_t)(vrow * VROW + dp * 16 + vcol) * 2;
                    uint32_t vh_[4], vl_[4];
                    ldmx4t(vh_, st + 2 * KVTILE_B + off);
                    ldmx4t(vl_, st + 3 * KVTILE_B + off);
                    mma16816(o[dp*2 + 0], ph, vh_[0], vh_[1]);
                    mma16816(o[dp*2 + 0], ph, vl_[0], vl_[1]);
                    mma16816(o[dp*2 + 0], pl, vh_[0], vh_[1]);
                    mma16816(o[dp*2 + 1], ph, vh_[2], vh_[3]);
                    mma16816(o[dp*2 + 1], ph, vl_[2], vl_[3]);
                    mma16816(o[dp*2 + 1], pl, vh_[2], vh_[3]);
                }
            }
        }

        __syncthreads();
        if (j + 2 < ntiles) load_kv(j + 2, j & 1);
    }

    // ---- epilogue: out[b, n, h*64 + col] = O / l ----
    const int b = bh / HH, h = bh % HH;
    const float inv0 = 1.0f / li0, inv1 = 1.0f / li1;
    const int r0 = qbase + wm + (lane >> 2);
    const int c0 = (lane & 3) * 2;
    #pragma unroll
    for (int fn = 0; fn < 8; ++fn) {
        const int col = h * HD + fn * 8 + c0;
        float* d0 = out + ((size_t)(b * NN + r0)) * DD + col;
        float* d1 = out + ((size_t)(b * NN + r0 + 8)) * DD + col;
        *reinterpret_cast<float2*>(d0) = make_float2(o[fn][0] * inv0, o[fn][1] * inv0);
        *reinterpret_cast<float2*>(d1) = make_float2(o[fn][2] * inv1, o[fn][3] * inv1);
    }
}

static const int GEMM_SMEM  = 2 * STAGE_B;     // 81920
static const int FLASH_SMEM = 2 * KVSTAGE_B;   // 73728

extern "C" void kernel_launch(void* const* d_in, const int* in_sizes, int n_in,
                              void* d_out, int out_size)
{
    const float* x  = (const float*)d_in[0];
    const float* Wq = (const float*)d_in[1];
    const float* Wk = (const float*)d_in[2];
    const float* Wv = (const float*)d_in[3];
    float* out = (float*)d_out;

    cudaFuncSetAttribute(qkv_mma_kernel, cudaFuncAttributeMaxDynamicSharedMemorySize, GEMM_SMEM);
    cudaFuncSetAttribute(flash_mma_kernel, cudaFuncAttributeMaxDynamicSharedMemorySize, FLASH_SMEM);

    int total4 = XN / 4 + 3 * (WN / 4);
    split_kernel<<<(total4 + 255) / 256, 256>>>(
        (const float4*)x, (const float4*)Wq, (const float4*)Wk, (const float4*)Wv);

    qkv_mma_kernel<<<dim3(DD / 128, (BB * NN) / 128, 3), 256, GEMM_SMEM>>>();

    flash_mma_kernel<<<dim3(NN / 128, BH), 256, FLASH_SMEM>>>(out);
}

// round 5
// speedup vs baseline: 2.7762x; 1.0256x over previous
#include <cuda_runtime.h>
#include <cuda_bf16.h>
#include <cstdint>
#include <math.h>

// Problem constants
#define BB 2
#define NN 2048
#define DD 768
#define HH 12
#define HD 64
#define BH (BB*HH)
#define XN (BB*NN*DD)
#define WN (DD*DD)

// bf16 hi/lo splits of inputs
__device__ __align__(16) __nv_bfloat16 g_xhi[XN], g_xlo[XN];
__device__ __align__(16) __nv_bfloat16 g_whi[3 * WN], g_wlo[3 * WN];
// bf16 hi/lo Q,K,V in [b,h,n,hd]
__device__ __align__(16) __nv_bfloat16 g_qhi[BH*NN*HD], g_qlo[BH*NN*HD];
__device__ __align__(16) __nv_bfloat16 g_khi[BH*NN*HD], g_klo[BH*NN*HD];
__device__ __align__(16) __nv_bfloat16 g_vhi[BH*NN*HD], g_vlo[BH*NN*HD];

__device__ __forceinline__ uint32_t smem_u32(const void* p) {
    uint32_t a;
    asm("{ .reg .u64 t; cvta.to.shared.u64 t, %1; cvt.u32.u64 %0, t; }" : "=r"(a) : "l"(p));
    return a;
}
__device__ __forceinline__ uint32_t pack2(float a, float b) {
    __nv_bfloat162 t = __floats2bfloat162_rn(a, b);
    return *reinterpret_cast<uint32_t*>(&t);
}
__device__ __forceinline__ void split2(float a, float b, uint32_t& hp, uint32_t& lp) {
    __nv_bfloat16 ha = __float2bfloat16_rn(a), hb = __float2bfloat16_rn(b);
    __nv_bfloat162 hh; hh.x = ha; hh.y = hb;
    hp = *reinterpret_cast<uint32_t*>(&hh);
    lp = pack2(a - __bfloat162float(ha), b - __bfloat162float(hb));
}
__device__ __forceinline__ void cpa16(uint32_t dst, const void* src) {
    asm volatile("cp.async.cg.shared.global [%0], [%1], 16;" :: "r"(dst), "l"(src) : "memory");
}
__device__ __forceinline__ void cpa_commit() {
    asm volatile("cp.async.commit_group;" ::: "memory");
}
__device__ __forceinline__ void ldmx4(uint32_t* r, uint32_t addr) {
    asm volatile("ldmatrix.sync.aligned.m8n8.x4.shared.b16 {%0,%1,%2,%3}, [%4];"
        : "=r"(r[0]), "=r"(r[1]), "=r"(r[2]), "=r"(r[3]) : "r"(addr));
}
__device__ __forceinline__ void ldmx4t(uint32_t* r, uint32_t addr) {
    asm volatile("ldmatrix.sync.aligned.m8n8.x4.trans.shared.b16 {%0,%1,%2,%3}, [%4];"
        : "=r"(r[0]), "=r"(r[1]), "=r"(r[2]), "=r"(r[3]) : "r"(addr));
}
__device__ __forceinline__ void mma16816(float* c, const uint32_t* a, uint32_t b0, uint32_t b1) {
    asm volatile("mma.sync.aligned.m16n8k16.row.col.f32.bf16.bf16.f32 "
        "{%0,%1,%2,%3}, {%4,%5,%6,%7}, {%8,%9}, {%0,%1,%2,%3};"
        : "+f"(c[0]), "+f"(c[1]), "+f"(c[2]), "+f"(c[3])
        : "r"(a[0]), "r"(a[1]), "r"(a[2]), "r"(a[3]), "r"(b0), "r"(b1));
}

// ---------------------------------------------------------------------------
// Split kernel
// ---------------------------------------------------------------------------
__global__ __launch_bounds__(256) void split_kernel(
    const float4* __restrict__ x, const float4* __restrict__ Wq,
    const float4* __restrict__ Wk, const float4* __restrict__ Wv)
{
    const int nx = XN / 4, nw = WN / 4;
    int i = blockIdx.x * 256 + threadIdx.x;
    if (i >= nx + 3 * nw) return;

    float4 v;
    __nv_bfloat16 *hd, *ld;
    if (i < nx) {
        v = x[i];
        hd = g_xhi + (size_t)i * 4; ld = g_xlo + (size_t)i * 4;
    } else {
        int j = i - nx;
        int z = j / nw, r = j - z * nw;
        const float4* w = (z == 0) ? Wq : (z == 1) ? Wk : Wv;
        v = w[r];
        hd = g_whi + (size_t)z * WN + (size_t)r * 4;
        ld = g_wlo + (size_t)z * WN + (size_t)r * 4;
    }
    uint32_t h0, l0, h1, l1;
    split2(v.x, v.y, h0, l0);
    split2(v.z, v.w, h1, l1);
    *reinterpret_cast<uint2*>(hd) = make_uint2(h0, h1);
    *reinterpret_cast<uint2*>(ld) = make_uint2(l0, l1);
}

// ---------------------------------------------------------------------------
// QKV GEMM: 4 warps, warp tile 64x64, CTA 128x128, bf16x3, cp.async 2-stage.
// ---------------------------------------------------------------------------
#define KC 32
#define SROW 40
#define TILE_B (128 * SROW * 2)
#define STAGE_B (4 * TILE_B)
#define NCHUNK (DD / KC)

__global__ __launch_bounds__(128) void qkv_mma_kernel()
{
    extern __shared__ char smc[];
    const uint32_t sb = smem_u32(smc);

    const int tid = threadIdx.x;
    const int w = tid >> 5, lane = tid & 31;
    const int wm = (w >> 1) * 64;
    const int wn = (w & 1) * 64;
    const int z = blockIdx.z;
    const int n0 = blockIdx.x * 128;
    const int m0 = blockIdx.y * 128;

    const __nv_bfloat16* __restrict__ Bhp = g_whi + (size_t)z * WN;
    const __nv_bfloat16* __restrict__ Blp = g_wlo + (size_t)z * WN;

    auto load_chunk = [&](int kt, int stage) {
        const int kb = kt * KC;
        const uint32_t st = sb + stage * STAGE_B;
        #pragma unroll
        for (int i = 0; i < 4; ++i) {
            int id = tid + i * 128;
            int r = id >> 2, c = id & 3;
            uint32_t doff = (uint32_t)(r * 80 + c * 16);
            size_t gA = (size_t)(m0 + r) * DD + kb + c * 8;
            size_t gB = (size_t)(n0 + r) * DD + kb + c * 8;
            cpa16(st + 0 * TILE_B + doff, g_xhi + gA);
            cpa16(st + 1 * TILE_B + doff, g_xlo + gA);
            cpa16(st + 2 * TILE_B + doff, Bhp + gB);
            cpa16(st + 3 * TILE_B + doff, Blp + gB);
        }
        cpa_commit();
    };

    float acc[4][8][4] = {};

    load_chunk(0, 0);
    load_chunk(1, 1);

    const int lrow = lane & 15;
    const int lcol = ((lane >> 4) & 1) * 8;

    for (int kt = 0; kt < NCHUNK; ++kt) {
        if (kt < NCHUNK - 1)
            asm volatile("cp.async.wait_group 1;" ::: "memory");
        else
            asm volatile("cp.async.wait_group 0;" ::: "memory");
        __syncthreads();

        const uint32_t st = sb + (kt & 1) * STAGE_B;

        #pragma unroll
        for (int ks = 0; ks < 2; ++ks) {
            const int kc = ks * 16 + lcol;
            uint32_t bh[4][4], bl[4][4];
            #pragma unroll
            for (int fp = 0; fp < 4; ++fp) {
                uint32_t off = (uint32_t)((wn + fp * 16 + lrow) * SROW + kc) * 2;
                ldmx4(bh[fp], st + 2 * TILE_B + off);
                ldmx4(bl[fp], st + 3 * TILE_B + off);
            }
            #pragma unroll
            for (int fm = 0; fm < 4; ++fm) {
                uint32_t ah[4], al[4];
                uint32_t off = (uint32_t)((wm + fm * 16 + lrow) * SROW + kc) * 2;
                ldmx4(ah, st + 0 * TILE_B + off);
                ldmx4(al, st + 1 * TILE_B + off);
                #pragma unroll
                for (int fn = 0; fn < 8; ++fn) {
                    const int p = fn >> 1, f = fn & 1;
                    mma16816(acc[fm][fn], ah, bh[p][f], bh[p][f + 2]);
                    mma16816(acc[fm][fn], ah, bl[p][f], bl[p][f + 2]);
                    mma16816(acc[fm][fn], al, bh[p][f], bh[p][f + 2]);
                }
            }
        }
        __syncthreads();
        if (kt + 2 < NCHUNK) load_chunk(kt + 2, kt & 1);
    }

    // epilogue: split to bf16 hi/lo, store to [b,h,n,hd]
    __nv_bfloat16* Oh = (z == 0) ? g_qhi : (z == 1) ? g_khi : g_vhi;
    __nv_bfloat16* Ol = (z == 0) ? g_qlo : (z == 1) ? g_klo : g_vlo;
    const int trow = lane >> 2;
    const int tcol = (lane & 3) * 2;
    #pragma unroll
    for (int fm = 0; fm < 4; ++fm) {
        #pragma unroll
        for (int fn = 0; fn < 8; ++fn) {
            int o = n0 + wn + fn * 8 + tcol;
            int h = o >> 6, cb = o & 63;
            #pragma unroll
            for (int half = 0; half < 2; ++half) {
                int row = m0 + wm + fm * 16 + trow + half * 8;
                int b = row >> 11, n = row & (NN - 1);
                size_t idx = (((size_t)(b * HH + h)) * NN + n) * HD + cb;
                uint32_t hp, lp;
                split2(acc[fm][fn][half * 2], acc[fm][fn][half * 2 + 1], hp, lp);
                *reinterpret_cast<uint32_t*>(Oh + idx) = hp;
                *reinterpret_cast<uint32_t*>(Ol + idx) = lp;
            }
        }
    }
}

// ---------------------------------------------------------------------------
// Flash attention: 4 warps x M=32 rows (BLOCK_M=128), BLOCK_N=64, bf16x3.
// ---------------------------------------------------------------------------
#define VROW 72
#define KVTILE_B (64 * VROW * 2)
#define KVSTAGE_B (4 * KVTILE_B)

__global__ __launch_bounds__(128) void flash_mma_kernel(float* __restrict__ out)
{
    extern __shared__ char smc[];
    const uint32_t sb = smem_u32(smc);
    const int tid = threadIdx.x, wid = tid >> 5, lane = tid & 31;
    const int bh = blockIdx.y;
    const int qt = (int)gridDim.x - 1 - (int)blockIdx.x;   // heavy tiles first
    const int qbase = qt * 128;
    const int wm = wid * 32;

    const size_t base = (size_t)bh * NN * HD;
    const __nv_bfloat16* __restrict__ Qh = g_qhi + base;
    const __nv_bfloat16* __restrict__ Ql = g_qlo + base;
    const __nv_bfloat16* __restrict__ Kh = g_khi + base;
    const __nv_bfloat16* __restrict__ Kl = g_klo + base;
    const __nv_bfloat16* __restrict__ Vh = g_vhi + base;
    const __nv_bfloat16* __restrict__ Vl = g_vlo + base;

    // Q fragments: 2 m-frags of 16 rows each
    uint32_t qh[2][4][4], ql[2][4][4];
    {
        const int r0 = qbase + wm + (lane >> 2);
        const int c0 = (lane & 3) * 2;
        #pragma unroll
        for (int mf = 0; mf < 2; ++mf) {
            #pragma unroll
            for (int kk = 0; kk < 4; ++kk) {
                #pragma unroll
                for (int jj = 0; jj < 4; ++jj) {
                    int row = r0 + mf * 16 + (jj & 1) * 8;
                    int col = kk * 16 + c0 + (jj >> 1) * 8;
                    qh[mf][kk][jj] = *reinterpret_cast<const uint32_t*>(Qh + (size_t)row * HD + col);
                    ql[mf][kk][jj] = *reinterpret_cast<const uint32_t*>(Ql + (size_t)row * HD + col);
                }
            }
        }
    }

    auto load_kv = [&](int j, int stage) {
        const int kb = j * 64;
        const uint32_t st = sb + stage * KVSTAGE_B;
        #pragma unroll
        for (int i = 0; i < 4; ++i) {
            int id = tid + i * 128;
            int r = id >> 3, c = id & 7;
            uint32_t doff = (uint32_t)(r * 144 + c * 16);
            size_t go = (size_t)(kb + r) * HD + c * 8;
            cpa16(st + 0 * KVTILE_B + doff, Kh + go);
            cpa16(st + 1 * KVTILE_B + doff, Kl + go);
            cpa16(st + 2 * KVTILE_B + doff, Vh + go);
            cpa16(st + 3 * KVTILE_B + doff, Vl + go);
        }
        cpa_commit();
    };

    float o[2][8][4] = {};
    float mi[2][2], li[2][2];
    #pragma unroll
    for (int mf = 0; mf < 2; ++mf) {
        mi[mf][0] = mi[mf][1] = -1e30f;
        li[mf][0] = li[mf][1] = 0.0f;
    }

    const int ntiles = 2 * qt + 2;
    load_kv(0, 0);
    if (ntiles > 1) load_kv(1, 1);

    const int lrow = lane & 15;
    const int lcol = ((lane >> 4) & 1) * 8;
    const int vrow_base = (lane & 7) + ((lane >> 3) & 1) * 8;
    const int vcol = ((lane >> 4) & 1) * 8;

    for (int j = 0; j < ntiles; ++j) {
        if (j < ntiles - 1)
            asm volatile("cp.async.wait_group 1;" ::: "memory");
        else
            asm volatile("cp.async.wait_group 0;" ::: "memory");
        __syncthreads();

        const bool active = (64 * j <= qbase + wm + 31);
        const uint32_t st = sb + (j & 1) * KVSTAGE_B;

        if (active) {
            // ---- S = Q K^T (bf16x3) ----
            float s[2][8][4] = {};
            #pragma unroll
            for (int kk = 0; kk < 4; ++kk) {
                const int kc = kk * 16 + lcol;
                #pragma unroll
                for (int np = 0; np < 4; ++np) {
                    uint32_t bkh[4], bkl[4];
                    uint32_t off = (uint32_t)((np * 16 + lrow) * VROW + kc) * 2;
                    ldmx4(bkh, st + 0 * KVTILE_B + off);
                    ldmx4(bkl, st + 1 * KVTILE_B + off);
                    #pragma unroll
                    for (int f = 0; f < 2; ++f) {
                        const int fn = np * 2 + f;
                        #pragma unroll
                        for (int mf = 0; mf < 2; ++mf) {
                            mma16816(s[mf][fn], qh[mf][kk], bkh[f], bkh[f + 2]);
                            mma16816(s[mf][fn], qh[mf][kk], bkl[f], bkl[f + 2]);
                            mma16816(s[mf][fn], ql[mf][kk], bkh[f], bkh[f + 2]);
                        }
                    }
                }
            }

            // ---- causal mask ----
            if (64 * j + 63 > qbase + wm) {
                #pragma unroll
                for (int mf = 0; mf < 2; ++mf) {
                    const int rg0 = qbase + wm + mf * 16 + (lane >> 2);
                    #pragma unroll
                    for (int fn = 0; fn < 8; ++fn) {
                        const int cb = j * 64 + fn * 8 + (lane & 3) * 2;
                        if (cb + 0 > rg0)     s[mf][fn][0] = -1e30f;
                        if (cb + 1 > rg0)     s[mf][fn][1] = -1e30f;
                        if (cb + 0 > rg0 + 8) s[mf][fn][2] = -1e30f;
                        if (cb + 1 > rg0 + 8) s[mf][fn][3] = -1e30f;
                    }
                }
            }

            // ---- online softmax ----
            float al[2][2];
            #pragma unroll
            for (int mf = 0; mf < 2; ++mf) {
                float m0n = mi[mf][0], m1n = mi[mf][1];
                #pragma unroll
                for (int fn = 0; fn < 8; ++fn) {
                    m0n = fmaxf(m0n, fmaxf(s[mf][fn][0], s[mf][fn][1]));
                    m1n = fmaxf(m1n, fmaxf(s[mf][fn][2], s[mf][fn][3]));
                }
                m0n = fmaxf(m0n, __shfl_xor_sync(0xffffffffu, m0n, 1));
                m0n = fmaxf(m0n, __shfl_xor_sync(0xffffffffu, m0n, 2));
                m1n = fmaxf(m1n, __shfl_xor_sync(0xffffffffu, m1n, 1));
                m1n = fmaxf(m1n, __shfl_xor_sync(0xffffffffu, m1n, 2));

                al[mf][0] = __expf(mi[mf][0] - m0n);
                al[mf][1] = __expf(mi[mf][1] - m1n);
                mi[mf][0] = m0n; mi[mf][1] = m1n;

                float rs0 = 0.0f, rs1 = 0.0f;
                #pragma unroll
                for (int fn = 0; fn < 8; ++fn) {
                    s[mf][fn][0] = __expf(s[mf][fn][0] - m0n);
                    s[mf][fn][1] = __expf(s[mf][fn][1] - m0n);
                    s[mf][fn][2] = __expf(s[mf][fn][2] - m1n);
                    s[mf][fn][3] = __expf(s[mf][fn][3] - m1n);
                    rs0 += s[mf][fn][0] + s[mf][fn][1];
                    rs1 += s[mf][fn][2] + s[mf][fn][3];
                }
                rs0 += __shfl_xor_sync(0xffffffffu, rs0, 1);
                rs0 += __shfl_xor_sync(0xffffffffu, rs0, 2);
                rs1 += __shfl_xor_sync(0xffffffffu, rs1, 1);
                rs1 += __shfl_xor_sync(0xffffffffu, rs1, 2);
                li[mf][0] = li[mf][0] * al[mf][0] + rs0;
                li[mf][1] = li[mf][1] * al[mf][1] + rs1;

                #pragma unroll
                for (int fn = 0; fn < 8; ++fn) {
                    o[mf][fn][0] *= al[mf][0]; o[mf][fn][1] *= al[mf][0];
                    o[mf][fn][2] *= al[mf][1]; o[mf][fn][3] *= al[mf][1];
                }
            }

            // ---- O += P V (bf16x3; P from registers) ----
            #pragma unroll
            for (int kk = 0; kk < 4; ++kk) {
                uint32_t ph[2][4], pl[2][4];
                #pragma unroll
                for (int mf = 0; mf < 2; ++mf) {
                    split2(s[mf][2*kk    ][0], s[mf][2*kk    ][1], ph[mf][0], pl[mf][0]);
                    split2(s[mf][2*kk    ][2], s[mf][2*kk    ][3], ph[mf][1], pl[mf][1]);
                    split2(s[mf][2*kk + 1][0], s[mf][2*kk + 1][1], ph[mf][2], pl[mf][2]);
                    split2(s[mf][2*kk + 1][2], s[mf][2*kk + 1][3], ph[mf][3], pl[mf][3]);
                }
                #pragma unroll
                for (int dp = 0; dp < 4; ++dp) {
                    const int vrow = kk * 16 + vrow_base;
                    uint32_t off = (uint32_t)(vrow * VROW + dp * 16 + vcol) * 2;
                    uint32_t vh_[4], vl_[4];
                    ldmx4t(vh_, st + 2 * KVTILE_B + off);
                    ldmx4t(vl_, st + 3 * KVTILE_B + off);
                    #pragma unroll
                    for (int mf = 0; mf < 2; ++mf) {
                        mma16816(o[mf][dp*2 + 0], ph[mf], vh_[0], vh_[1]);
                        mma16816(o[mf][dp*2 + 0], ph[mf], vl_[0], vl_[1]);
                        mma16816(o[mf][dp*2 + 0], pl[mf], vh_[0], vh_[1]);
                        mma16816(o[mf][dp*2 + 1], ph[mf], vh_[2], vh_[3]);
                        mma16816(o[mf][dp*2 + 1], ph[mf], vl_[2], vl_[3]);
                        mma16816(o[mf][dp*2 + 1], pl[mf], vh_[2], vh_[3]);
                    }
                }
            }
        }

        __syncthreads();
        if (j + 2 < ntiles) load_kv(j + 2, j & 1);
    }

    // ---- epilogue ----
    const int b = bh / HH, h = bh % HH;
    const int c0 = (lane & 3) * 2;
    #pragma unroll
    for (int mf = 0; mf < 2; ++mf) {
        const float inv0 = 1.0f / li[mf][0], inv1 = 1.0f / li[mf][1];
        const int r0 = qbase + wm + mf * 16 + (lane >> 2);
        #pragma unroll
        for (int fn = 0; fn < 8; ++fn) {
            const int col = h * HD + fn * 8 + c0;
            float* d0 = out + ((size_t)(b * NN + r0)) * DD + col;
            float* d1 = out + ((size_t)(b * NN + r0 + 8)) * DD + col;
            *reinterpret_cast<float2*>(d0) = make_float2(o[mf][fn][0] * inv0, o[mf][fn][1] * inv0);
            *reinterpret_cast<float2*>(d1) = make_float2(o[mf][fn][2] * inv1, o[mf][fn][3] * inv1);
        }
    }
}

static const int GEMM_SMEM  = 2 * STAGE_B;     // 81920
static const int FLASH_SMEM = 2 * KVSTAGE_B;   // 73728

extern "C" void kernel_launch(void* const* d_in, const int* in_sizes, int n_in,
                              void* d_out, int out_size)
{
    const float* x  = (const float*)d_in[0];
    const float* Wq = (const float*)d_in[1];
    const float* Wk = (const float*)d_in[2];
    const float* Wv = (const float*)d_in[3];
    float* out = (float*)d_out;

    cudaFuncSetAttribute(qkv_mma_kernel, cudaFuncAttributeMaxDynamicSharedMemorySize, GEMM_SMEM);
    cudaFuncSetAttribute(flash_mma_kernel, cudaFuncAttributeMaxDynamicSharedMemorySize, FLASH_SMEM);

    int total4 = XN / 4 + 3 * (WN / 4);
    split_kernel<<<(total4 + 255) / 256, 256>>>(
        (const float4*)x, (const float4*)Wq, (const float4*)Wk, (const float4*)Wv);

    qkv_mma_kernel<<<dim3(DD / 128, (BB * NN) / 128, 3), 128, GEMM_SMEM>>>();

    flash_mma_kernel<<<dim3(NN / 128, BH), 128, FLASH_SMEM>>>(out);
}